// round 15
// baseline (speedup 1.0000x reference)
#include <cuda_runtime.h>

// FeedForwardAttention — algebraically reduced, single persistent kernel.
//   attns[b,q,:] = softmax_k(u . key[b,k]),  u = Wk^T fck_w
//   out[b,q,:]   = Wv @ (sum_k e_k value[b,k,:]) / (sum_k e_k) + bv  (q-independent)
// P1 load-balanced over ALL 148 blocks: 1024 16-row units, 136 blocks x 7 +
// 12 blocks x 6 (max 0.875 MB/block vs 1.0 MB before). A block may cross one
// batch boundary -> <=2 accumulator segments, reconstructed in P2 closed-form.

#define BB 8
#define LL 2048
#define CC 1024
#define GRID 148
#define TPB 512
#define P0B 128

__device__ float g_upart[P0B * CC];
__device__ float g_u[CC];
__device__ float g_vpart[GRID * 2 * CC];   // [block][seg][c]
__device__ float g_epart[GRID * 2];
__device__ float g_vbar[BB * CC];
__device__ float g_outs[BB * CC];
__device__ unsigned g_count = 0;
__device__ unsigned g_gen = 0;

__device__ __forceinline__ void grid_barrier() {
    __syncthreads();
    if (threadIdx.x == 0) {
        unsigned gen = *(volatile unsigned*)&g_gen;
        __threadfence();
        if (atomicAdd(&g_count, 1u) == GRID - 1) {
            atomicExch(&g_count, 0u);
            __threadfence();
            atomicAdd(&g_gen, 1u);
        } else {
            while (*(volatile unsigned*)&g_gen == gen) { }
            __threadfence();
        }
    }
    __syncthreads();
}

// unit range of block i: [u_start(i), u_start(i) + u_count(i))
__device__ __host__ __forceinline__ int u_start(int i) {
    return (i < 136) ? 7 * i : 952 + 6 * (i - 136);
}
__device__ __host__ __forceinline__ int u_count(int i) {
    return (i < 136) ? 7 : 6;
}

// Block-level flush: reduce 16 warp-partial acc[8] + e into vpart/epart[idx].
__device__ __forceinline__ void flush_seg(
    float4 acc[8], float e_acc, int idx, float4 (*sbuf)[CC / 4], float* sew)
{
    const int t = threadIdx.x, w = t >> 5, lane = t & 31;
    __syncthreads();
    if (w < 8) {
#pragma unroll
        for (int i = 0; i < 8; ++i) sbuf[w][lane + i * 32] = acc[i];
    }
    if (lane == 0) sew[w] = e_acc;
    __syncthreads();
    if (w >= 8) {
        int bf = w - 8;
#pragma unroll
        for (int i = 0; i < 8; ++i) {
            float4 c = sbuf[bf][lane + i * 32];
            c.x += acc[i].x; c.y += acc[i].y; c.z += acc[i].z; c.w += acc[i].w;
            sbuf[bf][lane + i * 32] = c;
        }
    }
    __syncthreads();
    if (t < 256) {
        float4 s = make_float4(0.f, 0.f, 0.f, 0.f);
#pragma unroll
        for (int j = 0; j < 8; ++j) {
            float4 c = sbuf[j][t];
            s.x += c.x; s.y += c.y; s.z += c.z; s.w += c.w;
        }
        ((float4*)g_vpart)[idx * 256 + t] = s;
    } else if (w == 8) {
        float s = (lane < 16) ? sew[lane] : 0.f;
#pragma unroll
        for (int o = 16; o; o >>= 1) s += __shfl_xor_sync(0xFFFFFFFFu, s, o);
        if (lane == 0) g_epart[idx] = s;
    }
    __syncthreads();
}

__global__ void __launch_bounds__(TPB, 1) k_fused(
    const float* __restrict__ key, const float* __restrict__ value,
    const float* __restrict__ Wk, const float* __restrict__ Wv,
    const float* __restrict__ bv, const float* __restrict__ fckw,
    float4* __restrict__ out)
{
    __shared__ float4 su4[CC / 4];      // 4KB staged u
    __shared__ float4 sbuf[8][CC / 4];  // 32KB warp-partial reduce
    __shared__ float  sew[16];
    __shared__ float  s_scale;

    const int bk = blockIdx.x, t = threadIdx.x;
    const int w = t >> 5, lane = t & 31;

    // ---- P0: u partials (128 blocks x 8 o-rows; thread covers 2 cols) -----
    if (bk < P0B) {
        int o0 = bk * 8;
        float a0 = 0.f, a1 = 0.f;
#pragma unroll
        for (int o = 0; o < 8; ++o) {
            float f = fckw[o0 + o];
            const float* wr = Wk + (size_t)(o0 + o) * CC;
            a0 += f * wr[t];
            a1 += f * wr[t + 512];
        }
        g_upart[bk * CC + t]       = a0;
        g_upart[bk * CC + t + 512] = a1;
    }
    grid_barrier();

    // ---- P0b: u reduce (8 blocks x 128 columns) ---------------------------
    if (bk < 8 && t < 128) {
        int c = bk * 128 + t;
        float acc = 0.f;
#pragma unroll
        for (int j = 0; j < P0B; ++j) acc += g_upart[j * CC + c];
        g_u[c] = acc;
    }
    grid_barrier();

    // ---- P1: fused pass, ALL 148 blocks, 16-row units ----------------------
    {
        if (t < 256) su4[t] = ((const float4*)g_u)[t];
        __syncthreads();
        const int u0 = u_start(bk);
        const int nu = u_count(bk);
        int seg = 0;

        float4 acc[8];
#pragma unroll
        for (int i = 0; i < 8; ++i) acc[i] = make_float4(0.f, 0.f, 0.f, 0.f);
        float e_acc = 0.f;

        for (int it = 0; it < nu; ++it) {
            const int unit = u0 + it;
            if (it > 0 && (unit & 127) == 0) {   // batch boundary: flush seg 0
                flush_seg(acc, e_acc, bk * 2, sbuf, sew);
                seg = 1;
#pragma unroll
                for (int i = 0; i < 8; ++i) acc[i] = make_float4(0.f, 0.f, 0.f, 0.f);
                e_acc = 0.f;
            }
            const int row = unit * 16 + w;
            const float4* kr = (const float4*)key + (size_t)row * 256;
            const float4* vr = (const float4*)value + (size_t)row * 256;
            float4 kv[8], vv[8];
#pragma unroll
            for (int i = 0; i < 8; ++i) kv[i] = kr[lane + i * 32];
#pragma unroll
            for (int i = 0; i < 8; ++i) vv[i] = vr[lane + i * 32];
            float d = 0.f;
#pragma unroll
            for (int i = 0; i < 8; ++i) {
                float4 uv = su4[lane + i * 32];
                d += kv[i].x * uv.x + kv[i].y * uv.y + kv[i].z * uv.z + kv[i].w * uv.w;
            }
#pragma unroll
            for (int o = 16; o; o >>= 1) d += __shfl_xor_sync(0xFFFFFFFFu, d, o);
            const float e = __expf(d);
            e_acc += e;
#pragma unroll
            for (int i = 0; i < 8; ++i) {
                acc[i].x += e * vv[i].x; acc[i].y += e * vv[i].y;
                acc[i].z += e * vv[i].z; acc[i].w += e * vv[i].w;
            }
        }
        flush_seg(acc, e_acc, bk * 2 + seg, sbuf, sew);
    }
    grid_barrier();

    // ---- P2: vbar[b][c] = sum(segments of batch b) / esum[b]  (8 blocks) --
    if (bk < BB) {
        float a0 = 0.f, a1 = 0.f;
        float es = 0.f;
        for (int i = 0; i < GRID; ++i) {
            const int us = u_start(i);
            const int bA = us >> 7;                      // 128 units per batch
            const int bL = (us + u_count(i) - 1) >> 7;
            if (bA == bk) {
                const float* vp = g_vpart + (size_t)(i * 2) * CC;
                a0 += vp[t]; a1 += vp[t + 512];
                es += g_epart[i * 2];
            }
            if (bL == bk && bL != bA) {
                const float* vp = g_vpart + (size_t)(i * 2 + 1) * CC;
                a0 += vp[t]; a1 += vp[t + 512];
                es += g_epart[i * 2 + 1];
            }
        }
        float inv = 1.f / es;
        g_vbar[bk * CC + t]       = a0 * inv;
        g_vbar[bk * CC + t + 512] = a1 * inv;
    }
    grid_barrier();

    // ---- P3: outs[b][d] = Wv[d] . vbar[b] + bv[d]  (64 blocks x 16 d) -----
    if (bk < 64) {
        int d = bk * 16 + w;
        const float4* wp = (const float4*)(Wv + (size_t)d * CC);
        const float4* vb = (const float4*)g_vbar;
        float acc[BB];
#pragma unroll
        for (int b = 0; b < BB; ++b) acc[b] = 0.f;
#pragma unroll
        for (int i = 0; i < 8; ++i) {
            int idx = lane + i * 32;
            float4 wv = wp[idx];
#pragma unroll
            for (int b = 0; b < BB; ++b) {
                float4 v = vb[b * 256 + idx];
                acc[b] += wv.x * v.x + wv.y * v.y + wv.z * v.z + wv.w * v.w;
            }
        }
#pragma unroll
        for (int b = 0; b < BB; ++b)
#pragma unroll
            for (int o = 16; o; o >>= 1)
                acc[b] += __shfl_xor_sync(0xFFFFFFFFu, acc[b], o);
        if (lane == 0) {
            float bias = bv[d];
#pragma unroll
            for (int b = 0; b < BB; ++b) g_outs[b * CC + d] = acc[b] + bias;
        }
    }
    grid_barrier();

    // ---- P4: broadcast outs[b,:] (64MB streaming write, cached rows) ------
    {
        const int i0 = bk * TPB + t;
        const int d4 = i0 & 255;        // fixed: stride 148*512 ≡ 0 mod 256
        const float4* os = (const float4*)g_outs;
        float4 r0 = os[0 * 256 + d4], r1 = os[1 * 256 + d4];
        float4 r2 = os[2 * 256 + d4], r3 = os[3 * 256 + d4];
        float4 r4 = os[4 * 256 + d4], r5 = os[5 * 256 + d4];
        float4 r6 = os[6 * 256 + d4], r7 = os[7 * 256 + d4];
        const int total4 = BB * LL * CC / 4;
        for (int i = i0; i < total4; i += GRID * TPB) {
            int b = i >> 19;
            float4 r = (b < 4) ? ((b < 2) ? (b == 0 ? r0 : r1) : (b == 2 ? r2 : r3))
                               : ((b < 6) ? (b == 4 ? r4 : r5) : (b == 6 ? r6 : r7));
            __stcs(out + i, r);
        }
    }
}

extern "C" void kernel_launch(void* const* d_in, const int* in_sizes, int n_in,
                              void* d_out, int out_size) {
    const float* key   = (const float*)d_in[1];
    const float* value = (const float*)d_in[2];
    const float* Wk    = (const float*)d_in[5];
    const float* Wv    = (const float*)d_in[7];
    const float* bv    = (const float*)d_in[8];
    const float* fckw  = (const float*)d_in[11];
    k_fused<<<GRID, TPB>>>(key, value, Wk, Wv, bv, fckw, (float4*)d_out);
}

// round 16
// speedup vs baseline: 1.3083x; 1.3083x over previous
#include <cuda_runtime.h>

// FeedForwardAttention — algebraically reduced, single persistent kernel.
//   attns[b,q,:] = softmax_k(u . key[b,k]),  u = Wk^T fck_w
//   out[b,q,:]   = Wv @ (sum_k e_k value[b,k,:]) / (sum_k e_k) + bv  (q-independent)
// Round-7 structure (best measured) + two work-reducing deltas:
//   P1 loads via __ldcs (single-use 128MB stream, evict-first),
//   P4 caches the 8 output rows in registers -> pure __stcs store stream.

#define BB 8
#define LL 2048
#define CC 1024
#define GRID 148
#define TPB 512
#define P0B 128
#define P1B 128

__device__ float g_upart[P0B * CC];
__device__ float g_u[CC];
__device__ float g_vpart[P1B * CC];
__device__ float g_eblk[P1B];
__device__ float g_vbar[BB * CC];
__device__ float g_outs[BB * CC];
__device__ unsigned g_count = 0;
__device__ unsigned g_gen = 0;

__device__ __forceinline__ void grid_barrier() {
    __syncthreads();
    if (threadIdx.x == 0) {
        unsigned gen = *(volatile unsigned*)&g_gen;
        __threadfence();
        if (atomicAdd(&g_count, 1u) == GRID - 1) {
            atomicExch(&g_count, 0u);
            __threadfence();
            atomicAdd(&g_gen, 1u);
        } else {
            while (*(volatile unsigned*)&g_gen == gen) { }
            __threadfence();
        }
    }
    __syncthreads();
}

__global__ void __launch_bounds__(TPB, 1) k_fused(
    const float* __restrict__ key, const float* __restrict__ value,
    const float* __restrict__ Wk, const float* __restrict__ Wv,
    const float* __restrict__ bv, const float* __restrict__ fckw,
    float4* __restrict__ out)
{
    __shared__ float4 su4[CC / 4];      // 4KB staged u
    __shared__ float4 sbuf[8][CC / 4];  // 32KB warp-partial reduce
    __shared__ float  sew[16];
    __shared__ float  s_scale;

    const int bk = blockIdx.x, t = threadIdx.x;
    const int w = t >> 5, lane = t & 31;

    // ---- P0: u partials (128 blocks x 8 o-rows; thread covers 2 cols) -----
    if (bk < P0B) {
        int o0 = bk * 8;
        float a0 = 0.f, a1 = 0.f;
#pragma unroll
        for (int o = 0; o < 8; ++o) {
            float f = fckw[o0 + o];
            const float* wr = Wk + (size_t)(o0 + o) * CC;
            a0 += f * wr[t];
            a1 += f * wr[t + 512];
        }
        g_upart[bk * CC + t]       = a0;
        g_upart[bk * CC + t + 512] = a1;
    }
    grid_barrier();

    // ---- P0b: u reduce (8 blocks x 128 columns) ---------------------------
    if (bk < 8 && t < 128) {
        int c = bk * 128 + t;
        float acc = 0.f;
#pragma unroll
        for (int j = 0; j < P0B; ++j) acc += g_upart[j * CC + c];
        g_u[c] = acc;
    }
    grid_barrier();

    // ---- P1: fused, warp-local, batched loads (128 blocks x 128 rows) -----
    if (bk < P1B) {
        if (t < 256) su4[t] = ((const float4*)g_u)[t];
        __syncthreads();
        const int b = bk >> 4;
        const int row0 = b * LL + (bk & 15) * 128;

        float4 acc[8];
#pragma unroll
        for (int i = 0; i < 8; ++i) acc[i] = make_float4(0.f, 0.f, 0.f, 0.f);
        float e_acc = 0.f;

#pragma unroll 2
        for (int it = 0; it < 8; ++it) {
            const int row = row0 + it * 16 + w;
            const float4* kr = (const float4*)key + (size_t)row * 256;
            const float4* vr = (const float4*)value + (size_t)row * 256;
            float4 kv[8], vv[8];
#pragma unroll
            for (int i = 0; i < 8; ++i) kv[i] = __ldcs(kr + lane + i * 32);
#pragma unroll
            for (int i = 0; i < 8; ++i) vv[i] = __ldcs(vr + lane + i * 32);
            float d = 0.f;
#pragma unroll
            for (int i = 0; i < 8; ++i) {
                float4 uv = su4[lane + i * 32];
                d += kv[i].x * uv.x + kv[i].y * uv.y + kv[i].z * uv.z + kv[i].w * uv.w;
            }
#pragma unroll
            for (int o = 16; o; o >>= 1) d += __shfl_xor_sync(0xFFFFFFFFu, d, o);
            const float e = __expf(d);
            e_acc += e;
#pragma unroll
            for (int i = 0; i < 8; ++i) {
                acc[i].x += e * vv[i].x; acc[i].y += e * vv[i].y;
                acc[i].z += e * vv[i].z; acc[i].w += e * vv[i].w;
            }
        }

        // reduce 16 warp partials -> 8 bufs -> 1
        if (w < 8) {
#pragma unroll
            for (int i = 0; i < 8; ++i) sbuf[w][lane + i * 32] = acc[i];
        }
        if (lane == 0) sew[w] = e_acc;
        __syncthreads();
        if (w >= 8) {
            int bf = w - 8;
#pragma unroll
            for (int i = 0; i < 8; ++i) {
                float4 c = sbuf[bf][lane + i * 32];
                c.x += acc[i].x; c.y += acc[i].y; c.z += acc[i].z; c.w += acc[i].w;
                sbuf[bf][lane + i * 32] = c;
            }
        }
        __syncthreads();
        if (t < 256) {
            float4 s = make_float4(0.f, 0.f, 0.f, 0.f);
#pragma unroll
            for (int j = 0; j < 8; ++j) {
                float4 c = sbuf[j][t];
                s.x += c.x; s.y += c.y; s.z += c.z; s.w += c.w;
            }
            ((float4*)g_vpart)[bk * 256 + t] = s;
        } else if (w == 8) {
            float s = (lane < 16) ? sew[lane] : 0.f;
#pragma unroll
            for (int o = 16; o; o >>= 1) s += __shfl_xor_sync(0xFFFFFFFFu, s, o);
            if (lane == 0) g_eblk[bk] = s;
        }
    }
    grid_barrier();

    // ---- P2: vbar[b][c] = sum_j vpart / esum[b]  (8 blocks) ---------------
    if (bk < BB) {
        if (t == 0) {
            float es = 0.f;
#pragma unroll
            for (int j = 0; j < 16; ++j) es += g_eblk[bk * 16 + j];
            s_scale = 1.f / es;
        }
        float a0 = 0.f, a1 = 0.f;
#pragma unroll
        for (int j = 0; j < 16; ++j) {
            const float* vp = g_vpart + (size_t)(bk * 16 + j) * CC;
            a0 += vp[t];
            a1 += vp[t + 512];
        }
        __syncthreads();
        g_vbar[bk * CC + t]       = a0 * s_scale;
        g_vbar[bk * CC + t + 512] = a1 * s_scale;
    }
    grid_barrier();

    // ---- P3: outs[b][d] = Wv[d] . vbar[b] + bv[d]  (64 blocks x 16 d) -----
    if (bk < 64) {
        int d = bk * 16 + w;
        const float4* wp = (const float4*)(Wv + (size_t)d * CC);
        const float4* vb = (const float4*)g_vbar;
        float acc[BB];
#pragma unroll
        for (int b = 0; b < BB; ++b) acc[b] = 0.f;
#pragma unroll
        for (int i = 0; i < 8; ++i) {
            int idx = lane + i * 32;
            float4 wv = wp[idx];
#pragma unroll
            for (int b = 0; b < BB; ++b) {
                float4 v = vb[b * 256 + idx];
                acc[b] += wv.x * v.x + wv.y * v.y + wv.z * v.z + wv.w * v.w;
            }
        }
#pragma unroll
        for (int b = 0; b < BB; ++b)
#pragma unroll
            for (int o = 16; o; o >>= 1)
                acc[b] += __shfl_xor_sync(0xFFFFFFFFu, acc[b], o);
        if (lane == 0) {
            float bias = bv[d];
#pragma unroll
            for (int b = 0; b < BB; ++b) g_outs[b * CC + d] = acc[b] + bias;
        }
    }
    grid_barrier();

    // ---- P4: broadcast outs[b,:] (64MB write, cached rows, pure stcs) -----
    {
        const int i0 = bk * TPB + t;
        const int d4 = i0 & 255;        // fixed: stride 148*512 ≡ 0 mod 256
        const float4* os = (const float4*)g_outs;
        float4 r0 = os[0 * 256 + d4], r1 = os[1 * 256 + d4];
        float4 r2 = os[2 * 256 + d4], r3 = os[3 * 256 + d4];
        float4 r4 = os[4 * 256 + d4], r5 = os[5 * 256 + d4];
        float4 r6 = os[6 * 256 + d4], r7 = os[7 * 256 + d4];
        const int total4 = BB * LL * CC / 4;
        for (int i = i0; i < total4; i += GRID * TPB) {
            int b = i >> 19;
            float4 r = (b < 4) ? ((b < 2) ? (b == 0 ? r0 : r1) : (b == 2 ? r2 : r3))
                               : ((b < 6) ? (b == 4 ? r4 : r5) : (b == 6 ? r6 : r7));
            __stcs(out + i, r);
        }
    }
}

extern "C" void kernel_launch(void* const* d_in, const int* in_sizes, int n_in,
                              void* d_out, int out_size) {
    const float* key   = (const float*)d_in[1];
    const float* value = (const float*)d_in[2];
    const float* Wk    = (const float*)d_in[5];
    const float* Wv    = (const float*)d_in[7];
    const float* bv    = (const float*)d_in[8];
    const float* fckw  = (const float*)d_in[11];
    k_fused<<<GRID, TPB>>>(key, value, Wk, Wv, bv, fckw, (float4*)d_out);
}